// round 12
// baseline (speedup 1.0000x reference)
#include <cuda_runtime.h>

#define BATCH 64
#define NN 512
#define NDIAG 1023
#define NEGV  (-1e30f)
#define INV_LN2 1.44269504088896340736f
#define LN2F    0.69314718055994530942f

// Diagonal-major layout for DP outputs: (k, i) -> k*NN + i.
__device__ float g_f[(size_t)BATCH * NDIAG * NN];      // forward DP (log2 domain)
__device__ float g_b[(size_t)BATCH * NDIAG * NN];      // backward DP MINUS d (log2)
__device__ float g_max;                                // global logit max (log2)

__device__ __forceinline__ float ex2f(float x) {
    float y; asm("ex2.approx.ftz.f32 %0, %1;" : "=f"(y) : "f"(x)); return y;
}
__device__ __forceinline__ float lg2f(float x) {
    float y; asm("lg2.approx.ftz.f32 %0, %1;" : "=f"(y) : "f"(x)); return y;
}

__device__ __forceinline__ float lse_cell(float dg, float up, float lf, float dcur) {
    float hi1 = fmaxf(dg, up);
    float lo1 = fminf(dg, up);
    float m   = fmaxf(hi1, lf);
    float o2  = fminf(hi1, lf);
    float s = ex2f(lo1 - m) + ex2f(o2 - m);   // third term is 2^0 = 1
    return dcur + m + lg2f(1.0f + s);
}

// ---------------------------------------------------------------------------
// Load one round's aligned 8-float D window for both rows of a thread,
// directly from row-major D. Fwd: cols [jE0, jE0+7] ascending. Bwd: the
// mirrored cols [511-jE0-7, 511-jE0] descending (components swapped so the
// result array is always in diagonal-consumption order). Cols are clamped to
// stay in-allocation; clamped values are only consumed by invalid cells.
// ---------------------------------------------------------------------------
template<bool BWD>
__device__ __forceinline__ void load_win(const float* __restrict__ rowE,
                                         const float* __restrict__ rowO,
                                         int jE0, float* wE, float* wO) {
#pragma unroll
    for (int m = 0; m < 4; m++) {
        int c = BWD ? (510 - jE0 - 2 * m) : (jE0 + 2 * m);
        c = min(max(c, 0), 510);              // stays even -> float2 aligned
        float2 ve = *(const float2*)(rowE + c);
        float2 vo = *(const float2*)(rowO + c);
        if (!BWD) {
            wE[2 * m] = ve.x; wE[2 * m + 1] = ve.y;
            wO[2 * m] = vo.x; wO[2 * m + 1] = vo.y;
        } else {
            wE[2 * m] = ve.y; wE[2 * m + 1] = ve.x;
            wO[2 * m] = vo.y; wO[2 * m + 1] = vo.x;
        }
    }
}

// ---------------------------------------------------------------------------
// Wavefront DP: 256 threads, thread t owns rows (2t, 2t+1). Odd-row cell uses
// register inputs only; even-row cell needs 2 LDS from the neighbor thread's
// published odd-row values (diags k-1, k-2). 4 rotating smem buffers with
// static selectors; k-loop unrolled x8; D read straight from row-major input
// via per-round aligned windows (double-buffered, one-register carry for the
// odd row's off-by-one window). One CTA per (batch, direction).
// Backward CTAs write (val - d) so combine never re-reads d.
// ---------------------------------------------------------------------------
template<bool BWD>
__device__ __forceinline__ void dp_impl(int b, const float* __restrict__ D,
                                        float (*bufs)[258]) {
    const float* Db = D + (size_t)b * NN * NN;
    float* out = (BWD ? g_b : g_f) + (size_t)b * NDIAG * NN;
    int t = threadIdx.x;
    int iE = 2 * t;                   // even row; odd row = iE + 1
    const float* rowE = Db + (size_t)(BWD ? (511 - iE) : iE) * NN;
    const float* rowO = Db + (size_t)(BWD ? (510 - iE) : (iE + 1)) * NN;

    float curE[8], curO[8], nxtE[8], nxtO[8];
    load_win<BWD>(rowE, rowO, -iE, curE, curO);       // round 0 window
    float carryO = NEGV;              // col jE0-1; only consumed when valid
    float vE1 = NEGV, vE2 = NEGV, vO1 = NEGV, vO2 = NEGV;

    for (int tt = 0; tt < 128; tt++) {
        load_win<BWD>(rowE, rowO, 8 * (tt + 1) - iE, nxtE, nxtO);
#pragma unroll
        for (int p = 0; p < 8; p++) {
            int k = tt * 8 + p;                  // k==1023 is a no-op pad
            if (k < NDIAG) {                     // uniform over the block
                float dE = curE[p] * INV_LN2;
                float dO = ((p == 0) ? carryO : curO[p - 1]) * INV_LN2;
                float* bc        = bufs[p & 3];          // diag k
                const float* b1p = bufs[(p + 3) & 3];    // diag k-1
                const float* b2p = bufs[(p + 2) & 3];    // diag k-2

                float nb1 = b1p[1 + t];   // v(iE-1, k-1)  (t=0 -> NEG slot)
                float nb2 = b2p[1 + t];   // v(iE-1, k-2)

                int jE = k - iE;
                int jO = jE - 1;

                // even cell (iE, jE): up=nb1, dg=nb2, lf=vE1
                float dgE = (jE == 0) ? ((iE == 0) ? 0.0f : NEGV) : nb2;
                float lfE = (jE == 0) ? NEGV : vE1;
                float vE  = lse_cell(dgE, nb1, lfE, dE);
                vE = (jE >= 0 && jE < NN) ? vE : NEGV;

                // odd cell (iE+1, jO): up=vE1, dg=vE2, lf=vO1 (all registers)
                float dgO = (jO == 0) ? NEGV : vE2;
                float lfO = (jO == 0) ? NEGV : vO1;
                float vO  = lse_cell(dgO, vE1, lfO, dO);
                vO = (jO >= 0 && jO < NN) ? vO : NEGV;

                bc[2 + t] = vO;                   // publish odd-row value
                if (k >= iE && k <= iE + NN) {    // either row in range
                    float2 st;
                    st.x = BWD ? (vE - dE) : vE;
                    st.y = BWD ? (vO - dO) : vO;
                    *(float2*)(out + (size_t)k * NN + iE) = st;
                }
                vE2 = vE1; vE1 = vE;
                vO2 = vO1; vO1 = vO;
                __syncthreads();
            }
        }
        carryO = curO[7];
#pragma unroll
        for (int q = 0; q < 8; q++) { curE[q] = nxtE[q]; curO[q] = nxtO[q]; }
    }
}

__global__ void __launch_bounds__(256) dp_kernel(const float* __restrict__ D) {
    __shared__ float bufs[4][258];   // [rot][2 + t]; slots 0,1 = boundary NEG
    int bx = blockIdx.x;
    int b = bx >> 1, dir = bx & 1;
    float* bp = &bufs[0][0];
    for (int q = threadIdx.x; q < 4 * 258; q += 256) bp[q] = NEGV;
    __syncthreads();
    if (dir) dp_impl<true>(b, D, bufs);
    else     dp_impl<false>(b, D, bufs);
}

// ---------------------------------------------------------------------------
// Global max: every path passes through the corner cell, so
// max logit = f(N-1, M-1) maximized over batches.
// ---------------------------------------------------------------------------
__global__ void max_kernel() {
    int t = threadIdx.x;   // 32 threads
    float m = -3.4e38f;
    for (int b = t; b < BATCH; b += 32)
        m = fmaxf(m, g_f[(size_t)b * NDIAG * NN + (size_t)1022 * NN + 511]);
#pragma unroll
    for (int o = 16; o > 0; o >>= 1)
        m = fmaxf(m, __shfl_xor_sync(0xffffffffu, m, o));
    if (t == 0) g_max = m;
}

// ---------------------------------------------------------------------------
// Combine + finish fused: out = (f2 + (b2-d2) - max2) * ln2, de-diagonalized
// to row-major via a padded smem tile.
// ---------------------------------------------------------------------------
__global__ void __launch_bounds__(256) combine_kernel(float* __restrict__ out) {
    __shared__ float tile[32][257];
    int b = blockIdx.y;
    int k0 = blockIdx.x * 32;
    const float* fd = g_f + (size_t)b * NDIAG * NN;
    const float* bd = g_b + (size_t)b * NDIAG * NN;
    float* ob = out + (size_t)b * NN * NN;
    int tid = threadIdx.x, lane = tid & 31, w = tid >> 5;
    float mx = g_max;

    for (int ih = 0; ih < 2; ih++) {
        int ibase = ih * 256;
        for (int kk = 0; kk < 32; kk++) {
            int k = k0 + kk;
            int i = ibase + tid;
            int j = k - i;
            float v = 0.0f;
            if (j >= 0 && j < NN) {
                int a = k * NN + i;
                v = (fd[a] + bd[(1022 - k) * NN + (511 - i)] - mx) * LN2F;
            }
            tile[kk][tid] = v;
        }
        __syncthreads();
        for (int rr = 0; rr < 32; rr++) {
            int i = ibase + w * 32 + rr;
            int jlo = max(0, k0 - i);
            int jhi = min(NN - 1, k0 + 31 - i);
            int j = jlo + lane;
            if (j <= jhi) {
                int kk = i + j - k0;
                ob[(size_t)i * NN + j] = tile[kk][i - ibase];
            }
        }
        __syncthreads();
    }
}

extern "C" void kernel_launch(void* const* d_in, const int* in_sizes, int n_in,
                              void* d_out, int out_size) {
    const float* d = (const float*)d_in[0];
    float* out = (float*)d_out;

    dp_kernel<<<BATCH * 2, 256>>>(d);

    max_kernel<<<1, 32>>>();

    dim3 cgrid(32, BATCH);
    combine_kernel<<<cgrid, 256>>>(out);
}

// round 13
// speedup vs baseline: 1.2644x; 1.2644x over previous
#include <cuda_runtime.h>

#define BATCH 64
#define NN 512
#define NDIAG 1023
#define NEGV  (-1e30f)
#define INV_LN2 1.44269504088896340736f
#define LN2F    0.69314718055994530942f
#define SROW 516    // stage row stride: 516 mod 32 == 4 -> conflict-free STS

// Diagonal-major layout for DP outputs: (k, i) -> k*NN + i.
__device__ float g_f[(size_t)BATCH * NDIAG * NN];      // forward DP (log2 domain)
__device__ float g_b[(size_t)BATCH * NDIAG * NN];      // backward DP MINUS d (log2)
__device__ float g_max;                                // global logit max (log2)

__device__ __forceinline__ float ex2f(float x) {
    float y; asm("ex2.approx.ftz.f32 %0, %1;" : "=f"(y) : "f"(x)); return y;
}
__device__ __forceinline__ float lg2f(float x) {
    float y; asm("lg2.approx.ftz.f32 %0, %1;" : "=f"(y) : "f"(x)); return y;
}

__device__ __forceinline__ float lse_cell(float dg, float up, float lf, float dcur) {
    float hi1 = fmaxf(dg, up);
    float lo1 = fminf(dg, up);
    float m   = fmaxf(hi1, lf);
    float o2  = fminf(hi1, lf);
    float s = ex2f(lo1 - m) + ex2f(o2 - m);   // third term is 2^0 = 1
    return dcur + m + lg2f(1.0f + s);
}

// ---------------------------------------------------------------------------
// Cooperative stage loader: for round base diag kbase, fetch d(i, kbase+p-i)
// for all 512 rows x 8 phases, scaled by 1/ln2. 8 lanes per row -> the 8
// phase-values of one row are 8 consecutive floats in row-major D (reversed
// for BWD): fully coalesced (4 segments per warp). Out-of-range cols clamp
// in-allocation; those values are consumed only by invalid (discarded) cells.
// ---------------------------------------------------------------------------
template<bool BWD>
__device__ __forceinline__ void stage_fetch(const float* __restrict__ Db,
                                            int kbase, int t, float* vals) {
    int p = t & 7;
    int r0 = t >> 3;            // 0..31
#pragma unroll
    for (int q = 0; q < 16; q++) {
        int r = r0 + 32 * q;    // DP row
        int c = kbase + p - r;  // DP col
        int rg = BWD ? (511 - r) : r;
        int cg = BWD ? (511 - c) : c;
        cg = min(max(cg, 0), 511);
        vals[q] = Db[rg * NN + cg] * INV_LN2;
    }
}

// ---------------------------------------------------------------------------
// Wavefront DP: 256 threads, thread t owns rows (2t, 2t+1). Odd-row cell uses
// register inputs only; even-row cell takes 2 LDS from the neighbor thread's
// published odd-row values (diags k-1, k-2). 4 rotating smem buffers with
// static selectors; k-loop unrolled x8. D comes from a double-buffered smem
// stage filled cooperatively one round ahead (coalesced global reads,
// conflict-free STS/LDS). One CTA per (batch, direction).
// Backward CTAs write (val - d) so combine never re-reads d.
// ---------------------------------------------------------------------------
template<bool BWD>
__device__ __forceinline__ void dp_impl(int b, const float* __restrict__ D,
                                        float (*bufs)[258],
                                        float (*stage)[8][SROW]) {
    const float* Db = D + (size_t)b * NN * NN;
    float* out = (BWD ? g_b : g_f) + (size_t)b * NDIAG * NN;
    int t = threadIdx.x;
    int iE = 2 * t;                   // even row; odd row = iE + 1
    int lp = t & 7, lr = t >> 3;      // loader phase / row-group

    // stage round 0
    {
        float v0[16];
        stage_fetch<BWD>(Db, 0, t, v0);
#pragma unroll
        for (int q = 0; q < 16; q++) stage[0][lp][lr + 32 * q] = v0[q];
    }
    __syncthreads();

    float vE1 = NEGV, vE2 = NEGV;     // even row at diag k-1, k-2
    float vO1 = NEGV, vO2 = NEGV;     // odd  row at diag k-1, k-2

    for (int tt = 0; tt < 128; tt++) {
        float vals[16];
        stage_fetch<BWD>(Db, 8 * (tt + 1), t, vals);   // next round, in flight
        const int sb = tt & 1;
#pragma unroll
        for (int p = 0; p < 8; p++) {
            int k = tt * 8 + p;                  // k==1023 is a no-op pad
            if (k < NDIAG) {                     // uniform over the block
                float2 d2 = *(const float2*)&stage[sb][p][iE];
                float dE = d2.x, dO = d2.y;
                float* bc        = bufs[p & 3];          // diag k
                const float* b1p = bufs[(p + 3) & 3];    // diag k-1
                const float* b2p = bufs[(p + 2) & 3];    // diag k-2

                float nb1 = b1p[1 + t];   // v(iE-1, k-1)  (t=0 -> NEG slot)
                float nb2 = b2p[1 + t];   // v(iE-1, k-2)

                int jE = k - iE;
                int jO = jE - 1;

                // even cell (iE, jE): up=nb1, dg=nb2, lf=vE1
                float dgE = (jE == 0) ? ((iE == 0) ? 0.0f : NEGV) : nb2;
                float lfE = (jE == 0) ? NEGV : vE1;
                float vE  = lse_cell(dgE, nb1, lfE, dE);
                vE = (jE >= 0 && jE < NN) ? vE : NEGV;

                // odd cell (iE+1, jO): up=vE1, dg=vE2, lf=vO1 (all registers)
                float dgO = (jO == 0) ? NEGV : vE2;
                float lfO = (jO == 0) ? NEGV : vO1;
                float vO  = lse_cell(dgO, vE1, lfO, dO);
                vO = (jO >= 0 && jO < NN) ? vO : NEGV;

                bc[2 + t] = vO;                   // publish odd-row value
                if (k >= iE && k <= iE + NN) {    // either row in range
                    float2 st;
                    st.x = BWD ? (vE - dE) : vE;
                    st.y = BWD ? (vO - dO) : vO;
                    *(float2*)(out + (size_t)k * NN + iE) = st;
                }
                vE2 = vE1; vE1 = vE;
                vO2 = vO1; vO1 = vO;
            }
            if (p < 7) __syncthreads();
        }
        // publish next round's stage, then one barrier orders both the p=7
        // bufs writes and the stage flip.
#pragma unroll
        for (int q = 0; q < 16; q++) stage[sb ^ 1][lp][lr + 32 * q] = vals[q];
        __syncthreads();
    }
}

__global__ void __launch_bounds__(256) dp_kernel(const float* __restrict__ D) {
    __shared__ float bufs[4][258];       // [rot][2 + t]; slots 0,1 = NEG bound
    __shared__ float stage[2][8][SROW];  // double-buffered D windows
    int bx = blockIdx.x;
    int b = bx >> 1, dir = bx & 1;
    float* bp = &bufs[0][0];
    for (int q = threadIdx.x; q < 4 * 258; q += 256) bp[q] = NEGV;
    __syncthreads();
    if (dir) dp_impl<true>(b, D, bufs, stage);
    else     dp_impl<false>(b, D, bufs, stage);
}

// ---------------------------------------------------------------------------
// Global max: every path passes through the corner cell, so
// max logit = f(N-1, M-1) maximized over batches.
// ---------------------------------------------------------------------------
__global__ void max_kernel() {
    int t = threadIdx.x;   // 32 threads
    float m = -3.4e38f;
    for (int b = t; b < BATCH; b += 32)
        m = fmaxf(m, g_f[(size_t)b * NDIAG * NN + (size_t)1022 * NN + 511]);
#pragma unroll
    for (int o = 16; o > 0; o >>= 1)
        m = fmaxf(m, __shfl_xor_sync(0xffffffffu, m, o));
    if (t == 0) g_max = m;
}

// ---------------------------------------------------------------------------
// Combine + finish fused: out = (f2 + (b2-d2) - max2) * ln2, de-diagonalized
// to row-major via a padded smem tile.
// ---------------------------------------------------------------------------
__global__ void __launch_bounds__(256) combine_kernel(float* __restrict__ out) {
    __shared__ float tile[32][257];
    int b = blockIdx.y;
    int k0 = blockIdx.x * 32;
    const float* fd = g_f + (size_t)b * NDIAG * NN;
    const float* bd = g_b + (size_t)b * NDIAG * NN;
    float* ob = out + (size_t)b * NN * NN;
    int tid = threadIdx.x, lane = tid & 31, w = tid >> 5;
    float mx = g_max;

    for (int ih = 0; ih < 2; ih++) {
        int ibase = ih * 256;
        for (int kk = 0; kk < 32; kk++) {
            int k = k0 + kk;
            int i = ibase + tid;
            int j = k - i;
            float v = 0.0f;
            if (j >= 0 && j < NN) {
                int a = k * NN + i;
                v = (fd[a] + bd[(1022 - k) * NN + (511 - i)] - mx) * LN2F;
            }
            tile[kk][tid] = v;
        }
        __syncthreads();
        for (int rr = 0; rr < 32; rr++) {
            int i = ibase + w * 32 + rr;
            int jlo = max(0, k0 - i);
            int jhi = min(NN - 1, k0 + 31 - i);
            int j = jlo + lane;
            if (j <= jhi) {
                int kk = i + j - k0;
                ob[(size_t)i * NN + j] = tile[kk][i - ibase];
            }
        }
        __syncthreads();
    }
}

extern "C" void kernel_launch(void* const* d_in, const int* in_sizes, int n_in,
                              void* d_out, int out_size) {
    const float* d = (const float*)d_in[0];
    float* out = (float*)d_out;

    dp_kernel<<<BATCH * 2, 256>>>(d);

    max_kernel<<<1, 32>>>();

    dim3 cgrid(32, BATCH);
    combine_kernel<<<cgrid, 256>>>(out);
}

// round 14
// speedup vs baseline: 1.2927x; 1.0224x over previous
#include <cuda_runtime.h>

#define BATCH 64
#define NN 512
#define NDIAG 1023
#define NEGV  (-1e30f)
#define INV_LN2 1.44269504088896340736f
#define LN2F    0.69314718055994530942f
#define SROW 516    // stage row stride: 516 mod 32 == 4 -> conflict-free STS

// Diagonal-major layout for DP outputs: (k, i) -> k*NN + i.
__device__ float g_f[(size_t)BATCH * NDIAG * NN];      // forward DP (log2 domain)
__device__ float g_b[(size_t)BATCH * NDIAG * NN];      // backward DP MINUS d (log2)
__device__ float g_max;                                // global logit max (log2)

__device__ __forceinline__ float ex2f(float x) {
    float y; asm("ex2.approx.ftz.f32 %0, %1;" : "=f"(y) : "f"(x)); return y;
}
__device__ __forceinline__ float lg2f(float x) {
    float y; asm("lg2.approx.ftz.f32 %0, %1;" : "=f"(y) : "f"(x)); return y;
}

__device__ __forceinline__ float lse_cell(float dg, float up, float lf, float dcur) {
    float hi1 = fmaxf(dg, up);
    float lo1 = fminf(dg, up);
    float m   = fmaxf(hi1, lf);
    float o2  = fminf(hi1, lf);
    float s = ex2f(lo1 - m) + ex2f(o2 - m);   // third term is 2^0 = 1
    return dcur + m + lg2f(1.0f + s);
}

// ---------------------------------------------------------------------------
// Cooperative stage loader: for round base diag kbase, fetch d(i, kbase+p-i)
// for all 512 rows x 8 phases, scaled by 1/ln2. 8 lanes per row -> coalesced.
// Out-of-range cols clamp in-allocation; consumed only by invalid cells.
// ---------------------------------------------------------------------------
template<bool BWD>
__device__ __forceinline__ void stage_fetch(const float* __restrict__ Db,
                                            int kbase, int t, float* vals) {
    int p = t & 7;
    int r0 = t >> 3;            // 0..31
#pragma unroll
    for (int q = 0; q < 16; q++) {
        int r = r0 + 32 * q;    // DP row
        int c = kbase + p - r;  // DP col
        int rg = BWD ? (511 - r) : r;
        int cg = BWD ? (511 - c) : c;
        cg = min(max(cg, 0), 511);
        vals[q] = Db[rg * NN + cg] * INV_LN2;
    }
}

// ---------------------------------------------------------------------------
// Wavefront DP: 256 threads, thread t owns rows (2t, 2t+1). Odd-row cell uses
// register inputs only; even-row cell takes ONE LDS.64 (neighbor's odd-row
// values at diags k-1,k-2, published together as float2). Boundary (j==0)
// needs no selects: invalid cells carry NEGV through registers/buffers by
// construction, so raw reads give the right -inf surrogates; only the (0,0)
// seed is special-cased. 2 parity buffers (static selector); k-loop unrolled
// x8; D from the double-buffered coalesced smem stage. One CTA per
// (batch, direction). Backward CTAs write (val - d).
// ---------------------------------------------------------------------------
template<bool BWD>
__device__ __forceinline__ void dp_impl(int b, const float* __restrict__ D,
                                        float2 (*bufs2)[257],
                                        float (*stage)[8][SROW]) {
    const float* Db = D + (size_t)b * NN * NN;
    float* out = (BWD ? g_b : g_f) + (size_t)b * NDIAG * NN;
    int t = threadIdx.x;
    int iE = 2 * t;                   // even row; odd row = iE + 1
    int lp = t & 7, lr = t >> 3;      // loader phase / row-group

    {   // stage round 0
        float v0[16];
        stage_fetch<BWD>(Db, 0, t, v0);
#pragma unroll
        for (int q = 0; q < 16; q++) stage[0][lp][lr + 32 * q] = v0[q];
    }
    __syncthreads();

    float vE1 = NEGV, vE2 = NEGV;     // even row at diag k-1, k-2
    float vO1 = NEGV, vO2 = NEGV;     // odd  row at diag k-1, k-2

    for (int tt = 0; tt < 128; tt++) {
        float vals[16];
        stage_fetch<BWD>(Db, 8 * (tt + 1), t, vals);   // next round, in flight
        const int sb = tt & 1;
#pragma unroll
        for (int p = 0; p < 8; p++) {
            int k = tt * 8 + p;                  // k==1023 is a no-op pad
            if (k < NDIAG) {                     // uniform over the block
                float2 d2 = *(const float2*)&stage[sb][p][iE];
                float dE = d2.x, dO = d2.y;
                float2* wb        = bufs2[p & 1];        // diag k (parity)
                const float2* rb  = bufs2[(p + 1) & 1];  // diag k-1 (parity)

                float2 nb = rb[t];        // (vO(k-2), vO(k-1)) of row iE-1
                float nb2 = nb.x, nb1 = nb.y;

                int jE = k - iE;

                // even cell (iE, jE): up=nb1, dg=nb2, lf=vE1 (no selects;
                // invalid-cell NEGV invariant supplies boundary -infs)
                float dgE = nb2;
                if (k == 0 && t == 0) dgE = 0.0f;        // (0,0) seed
                float vE  = lse_cell(dgE, nb1, vE1, dE);
                vE = ((unsigned)jE < NN) ? vE : NEGV;

                // odd cell (iE+1, jE-1): up=vE1, dg=vE2, lf=vO1 (registers)
                float vO  = lse_cell(vE2, vE1, vO1, dO);
                vO = ((unsigned)(jE - 1) < NN) ? vO : NEGV;

                wb[1 + t] = make_float2(vO1, vO);        // publish (k-1, k)
                if ((unsigned)jE <= NN) {                // either row in range
                    float2 st;
                    st.x = BWD ? (vE - dE) : vE;
                    st.y = BWD ? (vO - dO) : vO;
                    *(float2*)(out + (size_t)k * NN + iE) = st;
                }
                vE2 = vE1; vE1 = vE;
                vO2 = vO1; vO1 = vO;
            }
            if (p < 7) __syncthreads();
        }
        // publish next round's stage; one barrier orders p=7 writes + flip
#pragma unroll
        for (int q = 0; q < 16; q++) stage[sb ^ 1][lp][lr + 32 * q] = vals[q];
        __syncthreads();
    }
}

__global__ void __launch_bounds__(256) dp_kernel(const float* __restrict__ D) {
    __shared__ float2 bufs2[2][257];     // [parity][1 + t]; slot 0 = NEG bound
    __shared__ float stage[2][8][SROW];  // double-buffered D windows
    int bx = blockIdx.x;
    int b = bx >> 1, dir = bx & 1;
    float* bp = (float*)&bufs2[0][0];
    for (int q = threadIdx.x; q < 2 * 257 * 2; q += 256) bp[q] = NEGV;
    __syncthreads();
    if (dir) dp_impl<true>(b, D, bufs2, stage);
    else     dp_impl<false>(b, D, bufs2, stage);
}

// ---------------------------------------------------------------------------
// Global max: every path passes through the corner cell, so
// max logit = f(N-1, M-1) maximized over batches.
// ---------------------------------------------------------------------------
__global__ void max_kernel() {
    int t = threadIdx.x;   // 32 threads
    float m = -3.4e38f;
    for (int b = t; b < BATCH; b += 32)
        m = fmaxf(m, g_f[(size_t)b * NDIAG * NN + (size_t)1022 * NN + 511]);
#pragma unroll
    for (int o = 16; o > 0; o >>= 1)
        m = fmaxf(m, __shfl_xor_sync(0xffffffffu, m, o));
    if (t == 0) g_max = m;
}

// ---------------------------------------------------------------------------
// Combine + finish fused: out = (f2 + (b2-d2) - max2) * ln2, de-diagonalized
// to row-major via a padded smem tile.
// ---------------------------------------------------------------------------
__global__ void __launch_bounds__(256) combine_kernel(float* __restrict__ out) {
    __shared__ float tile[32][257];
    int b = blockIdx.y;
    int k0 = blockIdx.x * 32;
    const float* fd = g_f + (size_t)b * NDIAG * NN;
    const float* bd = g_b + (size_t)b * NDIAG * NN;
    float* ob = out + (size_t)b * NN * NN;
    int tid = threadIdx.x, lane = tid & 31, w = tid >> 5;
    float mx = g_max;

    for (int ih = 0; ih < 2; ih++) {
        int ibase = ih * 256;
        for (int kk = 0; kk < 32; kk++) {
            int k = k0 + kk;
            int i = ibase + tid;
            int j = k - i;
            float v = 0.0f;
            if (j >= 0 && j < NN) {
                int a = k * NN + i;
                v = (fd[a] + bd[(1022 - k) * NN + (511 - i)] - mx) * LN2F;
            }
            tile[kk][tid] = v;
        }
        __syncthreads();
        for (int rr = 0; rr < 32; rr++) {
            int i = ibase + w * 32 + rr;
            int jlo = max(0, k0 - i);
            int jhi = min(NN - 1, k0 + 31 - i);
            int j = jlo + lane;
            if (j <= jhi) {
                int kk = i + j - k0;
                ob[(size_t)i * NN + j] = tile[kk][i - ibase];
            }
        }
        __syncthreads();
    }
}

extern "C" void kernel_launch(void* const* d_in, const int* in_sizes, int n_in,
                              void* d_out, int out_size) {
    const float* d = (const float*)d_in[0];
    float* out = (float*)d_out;

    dp_kernel<<<BATCH * 2, 256>>>(d);

    max_kernel<<<1, 32>>>();

    dim3 cgrid(32, BATCH);
    combine_kernel<<<cgrid, 256>>>(out);
}